// round 3
// baseline (speedup 1.0000x reference)
#include <cuda_runtime.h>
#include <math.h>

// Problem dims (fixed by the dataset)
#define T_STEPS 2048
#define BATCH   256
#define INP     256
#define HID     512
#define KTOT    (INP + HID)   // 768 concat K: [x_t | h]

// Tiling
#define BM 32          // batch tile
#define BJ 32          // hidden-column tile (covers 4 gate rows -> 128 W rows)
#define BK 32          // K tile
#define NKT (KTOT/BK)  // 24 k-tiles
#define NB  128        // grid: 16 x 8 blocks, all co-resident on 148 SMs

// Persistent state (device globals: allocation-free scratch)
__device__ float g_h0[BATCH * HID];
__device__ float g_h1[BATCH * HID];
__device__ float g_c [BATCH * HID];

// Grid barrier state (zero-initialized)
__device__ volatile int g_sense;
__device__ int          g_count;

__global__ void init_state_kernel(const float* __restrict__ h0,
                                  const float* __restrict__ c0) {
    int i = blockIdx.x * blockDim.x + threadIdx.x;
    if (i < BATCH * HID) {
        g_h0[i] = h0[i];
        g_c [i] = c0[i];
    }
}

// Persistent fused LSTM: all 2048 timesteps in ONE kernel.
// Grid: (16, 8) = 128 blocks x 256 threads, sense-reversing grid barrier between steps.
__global__ __launch_bounds__(256)
void lstm_persistent_kernel(const float* __restrict__ x_all,  // [T, BATCH, INP]
                            const float* __restrict__ W_ih,   // [4*HID, INP]
                            const float* __restrict__ W_hh,   // [4*HID, HID]
                            const float* __restrict__ b_ih,   // [4*HID]
                            const float* __restrict__ b_hh)   // [4*HID]
{
    __shared__ float As[2][BM][BK];        // double-buffered, xor-swizzled (16B units)
    __shared__ float Bs[2][4][BJ][BK];
    __shared__ int   s_ls;                 // block-local barrier sense

    const int tid   = threadIdx.x;
    const int jq    = tid & 15;            // 0..15 column lane
    const int bq    = tid >> 4;            // 0..15 batch lane
    const int jTile = blockIdx.x;          // 0..15
    const int bTile = blockIdx.y;          // 0..7

    // Load indices (shared by A and B tile loaders)
    const int lr  = tid >> 3;              // 0..31 row within tile
    const int lc4 = tid & 7;               // float4 slot 0..7
    const int swz = 4 * (lc4 ^ (lr & 7));  // swizzled float offset

    if (tid == 0) s_ls = g_sense;          // stable at launch start (stream-ordered)
    __syncthreads();

    // Per-block bias registers for the epilogue (constant across steps)
    float bias[4][2];
#pragma unroll
    for (int tt = 0; tt < 4; ++tt)
#pragma unroll
        for (int ji = 0; ji < 2; ++ji) {
            int jg = jTile * BJ + jq + ji * 16;
            bias[tt][ji] = b_ih[tt * HID + jg] + b_hh[tt * HID + jg];
        }

    for (int t = 0; t < T_STEPS; ++t) {
        const float* __restrict__ x_t   = x_all + (size_t)t * BATCH * INP;
        const float* __restrict__ h_in  = (t & 1) ? g_h1 : g_h0;
        float*       __restrict__ h_out = (t & 1) ? g_h0 : g_h1;

        float acc[4][2][2];
#pragma unroll
        for (int tt = 0; tt < 4; ++tt)
#pragma unroll
            for (int bi = 0; bi < 2; ++bi)
#pragma unroll
                for (int ji = 0; ji < 2; ++ji)
                    acc[tt][bi][ji] = 0.f;

        // ---- preload k-tile 0 into buffer 0 ----
        {
            int kg = lc4 * 4;  // tile 0 is pure x (kg < INP)
            *(float4*)&As[0][lr][swz] =
                *(const float4*)(x_t + (size_t)(bTile * BM + lr) * INP + kg);
#pragma unroll
            for (int tt = 0; tt < 4; ++tt) {
                int grow = tt * HID + jTile * BJ + lr;
                *(float4*)&Bs[0][tt][lr][swz] =
                    *(const float4*)(W_ih + (size_t)grow * INP + kg);
            }
        }
        __syncthreads();

        int buf = 0;
        for (int ktile = 0; ktile < NKT; ++ktile) {
            // ---- stage 1: issue LDGs for next tile into registers ----
            float4 na, nb0, nb1, nb2, nb3;
            if (ktile < NKT - 1) {
                int kg = (ktile + 1) * BK + lc4 * 4;
                if (kg < INP)
                    na = *(const float4*)(x_t + (size_t)(bTile * BM + lr) * INP + kg);
                else
                    na = *(const float4*)(h_in + (size_t)(bTile * BM + lr) * HID + (kg - INP));
                int g0 = 0 * HID + jTile * BJ + lr;
                int g1 = 1 * HID + jTile * BJ + lr;
                int g2 = 2 * HID + jTile * BJ + lr;
                int g3 = 3 * HID + jTile * BJ + lr;
                if (kg < INP) {
                    nb0 = *(const float4*)(W_ih + (size_t)g0 * INP + kg);
                    nb1 = *(const float4*)(W_ih + (size_t)g1 * INP + kg);
                    nb2 = *(const float4*)(W_ih + (size_t)g2 * INP + kg);
                    nb3 = *(const float4*)(W_ih + (size_t)g3 * INP + kg);
                } else {
                    int kh = kg - INP;
                    nb0 = *(const float4*)(W_hh + (size_t)g0 * HID + kh);
                    nb1 = *(const float4*)(W_hh + (size_t)g1 * HID + kh);
                    nb2 = *(const float4*)(W_hh + (size_t)g2 * HID + kh);
                    nb3 = *(const float4*)(W_hh + (size_t)g3 * HID + kh);
                }
            }

            // ---- stage 2: MMA on current buffer ----
#pragma unroll
            for (int k4 = 0; k4 < BK / 4; ++k4) {
                float4 a0 = *(const float4*)&As[buf][bq     ][4 * (k4 ^ (bq & 7))];
                float4 a1 = *(const float4*)&As[buf][bq + 16][4 * (k4 ^ (bq & 7))];
#pragma unroll
                for (int tt = 0; tt < 4; ++tt) {
                    float4 w0 = *(const float4*)&Bs[buf][tt][jq     ][4 * (k4 ^ (jq & 7))];
                    float4 w1 = *(const float4*)&Bs[buf][tt][jq + 16][4 * (k4 ^ (jq & 7))];
#define FMA4(ACC, A, W)                      \
                    ACC = fmaf(A.x, W.x, ACC);   \
                    ACC = fmaf(A.y, W.y, ACC);   \
                    ACC = fmaf(A.z, W.z, ACC);   \
                    ACC = fmaf(A.w, W.w, ACC);
                    FMA4(acc[tt][0][0], a0, w0)
                    FMA4(acc[tt][0][1], a0, w1)
                    FMA4(acc[tt][1][0], a1, w0)
                    FMA4(acc[tt][1][1], a1, w1)
#undef FMA4
                }
            }

            // ---- stage 3: commit staged tile to the other buffer ----
            if (ktile < NKT - 1) {
                int nb = buf ^ 1;
                *(float4*)&As[nb][lr][swz]     = na;
                *(float4*)&Bs[nb][0][lr][swz]  = nb0;
                *(float4*)&Bs[nb][1][lr][swz]  = nb1;
                *(float4*)&Bs[nb][2][lr][swz]  = nb2;
                *(float4*)&Bs[nb][3][lr][swz]  = nb3;
            }
            __syncthreads();
            buf ^= 1;
        }

        // ---- fused LSTM epilogue: block owns exactly its (b, j) cells; c is block-private ----
#pragma unroll
        for (int bi = 0; bi < 2; ++bi) {
#pragma unroll
            for (int ji = 0; ji < 2; ++ji) {
                int jg = jTile * BJ + jq + ji * 16;
                int bg = bTile * BM + bq + bi * 16;
                float gi = acc[0][bi][ji] + bias[0][ji];
                float gf = acc[1][bi][ji] + bias[1][ji];
                float gg = acc[2][bi][ji] + bias[2][ji];
                float go = acc[3][bi][ji] + bias[3][ji];
                float iv = 1.f / (1.f + expf(-gi));
                float fv = 1.f / (1.f + expf(-gf));
                float gv = tanhf(gg);
                float ov = 1.f / (1.f + expf(-go));
                size_t idx = (size_t)bg * HID + jg;
                float cn = fv * g_c[idx] + iv * gv;
                g_c[idx] = cn;
                h_out[idx] = ov * tanhf(cn);
            }
        }

        // ---- grid barrier (sense-reversing): h_out visible to all before next step ----
        __syncthreads();
        if (tid == 0) {
            int ls = s_ls ^ 1;
            s_ls = ls;
            __threadfence();                                   // publish h_out
            if (atomicAdd(&g_count, 1) == NB - 1) {
                g_count = 0;                                   // all arrived; safe to reset
                __threadfence();
                g_sense = ls;                                  // release
            } else {
                while (g_sense != ls) { }                      // spin (volatile)
                __threadfence();
            }
        }
        __syncthreads();
    }
}

// out[b] = h_last[b] . W_dec + b_dec   (h_last lives in g_h0 after 2048 steps)
__global__ void decode_kernel(const float* __restrict__ W_dec,
                              const float* __restrict__ b_dec,
                              float* __restrict__ out)
{
    int b = blockIdx.x;
    float s = 0.f;
    for (int k = threadIdx.x; k < HID; k += 128)
        s += g_h0[(size_t)b * HID + k] * W_dec[k];
    __shared__ float red[128];
    red[threadIdx.x] = s;
    __syncthreads();
#pragma unroll
    for (int off = 64; off > 0; off >>= 1) {
        if (threadIdx.x < off) red[threadIdx.x] += red[threadIdx.x + off];
        __syncthreads();
    }
    if (threadIdx.x == 0) out[b] = red[0] + b_dec[0];
}

extern "C" void kernel_launch(void* const* d_in, const int* in_sizes, int n_in,
                              void* d_out, int out_size)
{
    (void)in_sizes; (void)n_in; (void)out_size;
    const float* x     = (const float*)d_in[0];  // [T, B, I]
    const float* h0    = (const float*)d_in[1];  // [B, H]
    const float* c0    = (const float*)d_in[2];  // [B, H]
    const float* W_ih  = (const float*)d_in[3];  // [4H, I]
    const float* W_hh  = (const float*)d_in[4];  // [4H, H]
    const float* b_ih  = (const float*)d_in[5];  // [4H]
    const float* b_hh  = (const float*)d_in[6];  // [4H]
    const float* W_dec = (const float*)d_in[7];  // [1, H]
    const float* b_dec = (const float*)d_in[8];  // [1]
    float* out = (float*)d_out;                  // [B, 1]

    init_state_kernel<<<(BATCH * HID + 255) / 256, 256>>>(h0, c0);

    dim3 grid(HID / BJ, BATCH / BM);             // (16, 8) = 128 blocks, all co-resident
    lstm_persistent_kernel<<<grid, 256>>>(x, W_ih, W_hh, b_ih, b_hh);

    decode_kernel<<<BATCH, 128>>>(W_dec, b_dec, out);
}

// round 4
// speedup vs baseline: 1.0017x; 1.0017x over previous
#include <cuda_runtime.h>
#include <math.h>

// Problem dims (fixed by the dataset)
#define T_STEPS 2048
#define BATCH   256
#define INP     256
#define HID     512
#define KTOT    (INP + HID)   // 768 concat K: [x_t | h]

// Tiling
#define BM 32          // batch tile
#define BJ 32          // hidden-column tile (covers 4 gate rows -> 128 W rows)
#define BK 32          // K tile
#define NKT (KTOT/BK)  // 24 k-tiles
#define NB  128        // grid: 16 x 8 blocks, all co-resident on 148 SMs

// Persistent state (device globals: allocation-free scratch)
__device__ float g_h0[BATCH * HID];
__device__ float g_h1[BATCH * HID];
__device__ float g_c [BATCH * HID];

// Grid barrier state (zero-initialized)
__device__ volatile int g_sense;
__device__ int          g_count;

__global__ void init_state_kernel(const float* __restrict__ h0,
                                  const float* __restrict__ c0) {
    int i = blockIdx.x * blockDim.x + threadIdx.x;
    if (i < BATCH * HID) {
        g_h0[i] = h0[i];
        g_c [i] = c0[i];
    }
}

// Persistent fused LSTM: all 2048 timesteps in ONE kernel.
// Grid: (16, 8) = 128 blocks x 256 threads, sense-reversing grid barrier between steps.
__global__ __launch_bounds__(256)
void lstm_persistent_kernel(const float* __restrict__ x_all,  // [T, BATCH, INP]
                            const float* __restrict__ W_ih,   // [4*HID, INP]
                            const float* __restrict__ W_hh,   // [4*HID, HID]
                            const float* __restrict__ b_ih,   // [4*HID]
                            const float* __restrict__ b_hh)   // [4*HID]
{
    __shared__ float As[2][BM][BK];        // double-buffered, xor-swizzled (16B units)
    __shared__ float Bs[2][4][BJ][BK];
    __shared__ int   s_ls;                 // block-local barrier sense

    const int tid   = threadIdx.x;
    const int jq    = tid & 15;            // 0..15 column lane
    const int bq    = tid >> 4;            // 0..15 batch lane
    const int jTile = blockIdx.x;          // 0..15
    const int bTile = blockIdx.y;          // 0..7

    // Load indices (shared by A and B tile loaders)
    const int lr  = tid >> 3;              // 0..31 row within tile
    const int lc4 = tid & 7;               // float4 slot 0..7
    const int swz = 4 * (lc4 ^ (lr & 7));  // swizzled float offset

    if (tid == 0) s_ls = g_sense;          // stable at launch start (stream-ordered)
    __syncthreads();

    // Per-block bias registers for the epilogue (constant across steps)
    float bias[4][2];
#pragma unroll
    for (int tt = 0; tt < 4; ++tt)
#pragma unroll
        for (int ji = 0; ji < 2; ++ji) {
            int jg = jTile * BJ + jq + ji * 16;
            bias[tt][ji] = b_ih[tt * HID + jg] + b_hh[tt * HID + jg];
        }

    for (int t = 0; t < T_STEPS; ++t) {
        const float* __restrict__ x_t   = x_all + (size_t)t * BATCH * INP;
        const float* __restrict__ h_in  = (t & 1) ? g_h1 : g_h0;
        float*       __restrict__ h_out = (t & 1) ? g_h0 : g_h1;

        float acc[4][2][2];
#pragma unroll
        for (int tt = 0; tt < 4; ++tt)
#pragma unroll
            for (int bi = 0; bi < 2; ++bi)
#pragma unroll
                for (int ji = 0; ji < 2; ++ji)
                    acc[tt][bi][ji] = 0.f;

        // ---- preload k-tile 0 into buffer 0 ----
        {
            int kg = lc4 * 4;  // tile 0 is pure x (kg < INP)
            *(float4*)&As[0][lr][swz] =
                *(const float4*)(x_t + (size_t)(bTile * BM + lr) * INP + kg);
#pragma unroll
            for (int tt = 0; tt < 4; ++tt) {
                int grow = tt * HID + jTile * BJ + lr;
                *(float4*)&Bs[0][tt][lr][swz] =
                    *(const float4*)(W_ih + (size_t)grow * INP + kg);
            }
        }
        __syncthreads();

        int buf = 0;
        for (int ktile = 0; ktile < NKT; ++ktile) {
            // ---- stage 1: issue LDGs for next tile into registers ----
            float4 na, nb0, nb1, nb2, nb3;
            if (ktile < NKT - 1) {
                int kg = (ktile + 1) * BK + lc4 * 4;
                if (kg < INP)
                    na = *(const float4*)(x_t + (size_t)(bTile * BM + lr) * INP + kg);
                else
                    na = *(const float4*)(h_in + (size_t)(bTile * BM + lr) * HID + (kg - INP));
                int g0 = 0 * HID + jTile * BJ + lr;
                int g1 = 1 * HID + jTile * BJ + lr;
                int g2 = 2 * HID + jTile * BJ + lr;
                int g3 = 3 * HID + jTile * BJ + lr;
                if (kg < INP) {
                    nb0 = *(const float4*)(W_ih + (size_t)g0 * INP + kg);
                    nb1 = *(const float4*)(W_ih + (size_t)g1 * INP + kg);
                    nb2 = *(const float4*)(W_ih + (size_t)g2 * INP + kg);
                    nb3 = *(const float4*)(W_ih + (size_t)g3 * INP + kg);
                } else {
                    int kh = kg - INP;
                    nb0 = *(const float4*)(W_hh + (size_t)g0 * HID + kh);
                    nb1 = *(const float4*)(W_hh + (size_t)g1 * HID + kh);
                    nb2 = *(const float4*)(W_hh + (size_t)g2 * HID + kh);
                    nb3 = *(const float4*)(W_hh + (size_t)g3 * HID + kh);
                }
            }

            // ---- stage 2: MMA on current buffer ----
#pragma unroll
            for (int k4 = 0; k4 < BK / 4; ++k4) {
                float4 a0 = *(const float4*)&As[buf][bq     ][4 * (k4 ^ (bq & 7))];
                float4 a1 = *(const float4*)&As[buf][bq + 16][4 * (k4 ^ (bq & 7))];
#pragma unroll
                for (int tt = 0; tt < 4; ++tt) {
                    float4 w0 = *(const float4*)&Bs[buf][tt][jq     ][4 * (k4 ^ (jq & 7))];
                    float4 w1 = *(const float4*)&Bs[buf][tt][jq + 16][4 * (k4 ^ (jq & 7))];
#define FMA4(ACC, A, W)                      \
                    ACC = fmaf(A.x, W.x, ACC);   \
                    ACC = fmaf(A.y, W.y, ACC);   \
                    ACC = fmaf(A.z, W.z, ACC);   \
                    ACC = fmaf(A.w, W.w, ACC);
                    FMA4(acc[tt][0][0], a0, w0)
                    FMA4(acc[tt][0][1], a0, w1)
                    FMA4(acc[tt][1][0], a1, w0)
                    FMA4(acc[tt][1][1], a1, w1)
#undef FMA4
                }
            }

            // ---- stage 3: commit staged tile to the other buffer ----
            if (ktile < NKT - 1) {
                int nb = buf ^ 1;
                *(float4*)&As[nb][lr][swz]     = na;
                *(float4*)&Bs[nb][0][lr][swz]  = nb0;
                *(float4*)&Bs[nb][1][lr][swz]  = nb1;
                *(float4*)&Bs[nb][2][lr][swz]  = nb2;
                *(float4*)&Bs[nb][3][lr][swz]  = nb3;
            }
            __syncthreads();
            buf ^= 1;
        }

        // ---- fused LSTM epilogue: block owns exactly its (b, j) cells; c is block-private ----
#pragma unroll
        for (int bi = 0; bi < 2; ++bi) {
#pragma unroll
            for (int ji = 0; ji < 2; ++ji) {
                int jg = jTile * BJ + jq + ji * 16;
                int bg = bTile * BM + bq + bi * 16;
                float gi = acc[0][bi][ji] + bias[0][ji];
                float gf = acc[1][bi][ji] + bias[1][ji];
                float gg = acc[2][bi][ji] + bias[2][ji];
                float go = acc[3][bi][ji] + bias[3][ji];
                float iv = 1.f / (1.f + expf(-gi));
                float fv = 1.f / (1.f + expf(-gf));
                float gv = tanhf(gg);
                float ov = 1.f / (1.f + expf(-go));
                size_t idx = (size_t)bg * HID + jg;
                float cn = fv * g_c[idx] + iv * gv;
                g_c[idx] = cn;
                h_out[idx] = ov * tanhf(cn);
            }
        }

        // ---- grid barrier (sense-reversing): h_out visible to all before next step ----
        __syncthreads();
        if (tid == 0) {
            int ls = s_ls ^ 1;
            s_ls = ls;
            __threadfence();                                   // publish h_out
            if (atomicAdd(&g_count, 1) == NB - 1) {
                g_count = 0;                                   // all arrived; safe to reset
                __threadfence();
                g_sense = ls;                                  // release
            } else {
                while (g_sense != ls) { }                      // spin (volatile)
                __threadfence();
            }
        }
        __syncthreads();
    }
}

// out[b] = h_last[b] . W_dec + b_dec   (h_last lives in g_h0 after 2048 steps)
__global__ void decode_kernel(const float* __restrict__ W_dec,
                              const float* __restrict__ b_dec,
                              float* __restrict__ out)
{
    int b = blockIdx.x;
    float s = 0.f;
    for (int k = threadIdx.x; k < HID; k += 128)
        s += g_h0[(size_t)b * HID + k] * W_dec[k];
    __shared__ float red[128];
    red[threadIdx.x] = s;
    __syncthreads();
#pragma unroll
    for (int off = 64; off > 0; off >>= 1) {
        if (threadIdx.x < off) red[threadIdx.x] += red[threadIdx.x + off];
        __syncthreads();
    }
    if (threadIdx.x == 0) out[b] = red[0] + b_dec[0];
}

extern "C" void kernel_launch(void* const* d_in, const int* in_sizes, int n_in,
                              void* d_out, int out_size)
{
    (void)in_sizes; (void)n_in; (void)out_size;
    const float* x     = (const float*)d_in[0];  // [T, B, I]
    const float* h0    = (const float*)d_in[1];  // [B, H]
    const float* c0    = (const float*)d_in[2];  // [B, H]
    const float* W_ih  = (const float*)d_in[3];  // [4H, I]
    const float* W_hh  = (const float*)d_in[4];  // [4H, H]
    const float* b_ih  = (const float*)d_in[5];  // [4H]
    const float* b_hh  = (const float*)d_in[6];  // [4H]
    const float* W_dec = (const float*)d_in[7];  // [1, H]
    const float* b_dec = (const float*)d_in[8];  // [1]
    float* out = (float*)d_out;                  // [B, 1]

    init_state_kernel<<<(BATCH * HID + 255) / 256, 256>>>(h0, c0);

    dim3 grid(HID / BJ, BATCH / BM);             // (16, 8) = 128 blocks, all co-resident
    lstm_persistent_kernel<<<grid, 256>>>(x, W_ih, W_hh, b_ih, b_hh);

    decode_kernel<<<BATCH, 128>>>(W_dec, b_dec, out);
}

// round 5
// speedup vs baseline: 2.0736x; 2.0700x over previous
#include <cuda_runtime.h>
#include <cuda_bf16.h>
#include <math.h>
#include <stdint.h>

// Problem dims (fixed by dataset)
#define T_STEPS 2048
#define BATCH   256
#define INP     256
#define HID     512
#define KTOT    768            // concat K: [x_t | h]

// Partition: block = (jTile, bTile): 16 hidden cols x 64 batch rows
#define JT 16                  // hidden columns per block
#define BT 64                  // batch rows per block
#define NROWS 64               // gate rows per block = 4 gates * JT
#define KC 32                  // K chunk staged per iteration
#define NCH (KTOT / KC)        // 24 chunks
#define NBLK 128               // 32 x 4 grid, all co-resident (<=148 SMs)

// SMEM strides (in 32-bit words), padded for conflict-free fragment loads
#define W_STRIDE 388           // 384 words (768 bf16) + 4 pad  -> stride%32==4
#define A_STRIDE 20            // 16 words (32 bf16)  + 4 pad  -> stride%32==20
#define G_STRIDE 65            // gates buffer row stride (floats)

// SMEM layout (bytes)
#define SZ_W      (NROWS * W_STRIDE * 4)            // 99,328
#define OFF_WHI   0
#define OFF_WLO   (OFF_WHI + SZ_W)                  // 99,328
#define OFF_ABUF  (OFF_WLO + SZ_W)                  // 198,656
#define SZ_ABUF   (2 * 2 * BT * A_STRIDE * 4)       // 20,480 (dbuf x hi/lo x 64 x 20)
#define OFF_GATES OFF_ABUF                          // overlay (64*65*4 = 16,640 <= 20,480)
#define OFF_BIAS  (OFF_ABUF + SZ_ABUF)              // 219,136
#define OFF_SENSE (OFF_BIAS + NROWS * 4)            // 219,392
#define SMEM_BYTES (OFF_SENSE + 16)                 // 219,408

// Persistent state (device globals: allocation-free scratch)
__device__ float g_h0[BATCH * HID];
__device__ float g_h1[BATCH * HID];
__device__ float g_c [BATCH * HID];
__device__ volatile int g_sense;   // zero-init
__device__ int          g_count;   // zero-init

__global__ void init_state_kernel(const float* __restrict__ h0,
                                  const float* __restrict__ c0) {
    int i = blockIdx.x * blockDim.x + threadIdx.x;
    if (i < BATCH * HID) { g_h0[i] = h0[i]; g_c[i] = c0[i]; }
}

__device__ __forceinline__ uint32_t b2u(__nv_bfloat162 v) {
    return *reinterpret_cast<uint32_t*>(&v);
}

// split fp32 pair -> (hi bf16x2 word, lo bf16x2 word); low 16 bits = first (even-k) element
__device__ __forceinline__ void split2(float2 v, uint32_t& wh, uint32_t& wl) {
    __nv_bfloat162 hi2 = __floats2bfloat162_rn(v.x, v.y);
    float lx = v.x - __bfloat162float(__low2bfloat16(hi2));
    float ly = v.y - __bfloat162float(__high2bfloat16(hi2));
    __nv_bfloat162 lo2 = __floats2bfloat162_rn(lx, ly);
    wh = b2u(hi2); wl = b2u(lo2);
}

#define MMA_BF16(D, A, B0, B1)                                              \
    asm volatile("mma.sync.aligned.m16n8k16.row.col.f32.bf16.bf16.f32 "     \
                 "{%0,%1,%2,%3}, {%4,%5,%6,%7}, {%8,%9}, {%0,%1,%2,%3};"    \
                 : "+f"((D)[0]), "+f"((D)[1]), "+f"((D)[2]), "+f"((D)[3])   \
                 : "r"((A)[0]), "r"((A)[1]), "r"((A)[2]), "r"((A)[3]),      \
                   "r"(B0), "r"(B1));

// Persistent fused LSTM: tensor-core GEMM (bf16x3 ~ fp32), SMEM-resident weights,
// grid barrier between timesteps. Grid (32, 4) x 256 threads.
__global__ __launch_bounds__(256, 1)
void lstm_tc_kernel(const float* __restrict__ x_all,  // [T, BATCH, INP]
                    const float* __restrict__ W_ih,   // [4*HID, INP]
                    const float* __restrict__ W_hh,   // [4*HID, HID]
                    const float* __restrict__ b_ih,   // [4*HID]
                    const float* __restrict__ b_hh)   // [4*HID]
{
    extern __shared__ char sm[];
    uint32_t* Whi    = (uint32_t*)(sm + OFF_WHI);
    uint32_t* Wlo    = (uint32_t*)(sm + OFF_WLO);
    uint32_t* Ab     = (uint32_t*)(sm + OFF_ABUF);   // [(buf*2+hl)*BT + row]*A_STRIDE + col
    float*    gates  = (float*)   (sm + OFF_GATES);  // overlay on Ab
    float*    bias_s = (float*)   (sm + OFF_BIAS);
    int*      s_ls   = (int*)     (sm + OFF_SENSE);

    const int tid  = threadIdx.x;
    const int lane = tid & 31, warp = tid >> 5;
    const int wm = warp & 1;        // batch-half of the 64x64 tile
    const int wn = warp >> 1;       // 0..3: 16-gatecol slice
    const int lq  = lane >> 2;      // 0..7
    const int lr4 = lane & 3;       // 0..3
    const int jTile = blockIdx.x;   // 0..31
    const int bTile = blockIdx.y;   // 0..3

    // ---- one-time: load + split weights into SMEM (rows r = tt*16 + jj) ----
    {
        int r  = tid >> 2;                        // 0..63
        int grow = (r >> 4) * HID + jTile * JT + (r & 15);
        int kbase = (tid & 3) * 192;
        for (int i = 0; i < 96; ++i) {
            int k = kbase + 2 * i;
            float2 v = (k < INP)
                ? *(const float2*)(W_ih + (size_t)grow * INP + k)
                : *(const float2*)(W_hh + (size_t)grow * HID + (k - INP));
            uint32_t wh, wl; split2(v, wh, wl);
            Whi[r * W_STRIDE + k / 2] = wh;
            Wlo[r * W_STRIDE + k / 2] = wl;
        }
        if (tid < NROWS) {
            int gr = (tid >> 4) * HID + jTile * JT + (tid & 15);
            bias_s[tid] = b_ih[gr] + b_hh[gr];
        }
        if (tid == 0) *s_ls = g_sense;
    }
    __syncthreads();

    // staging assignment: 4 threads per batch row, 8 k-floats each
    const int srow  = tid >> 2;            // 0..63
    const int skoff = (tid & 3) * 8;       // k offset within chunk
    const int brow  = bTile * BT + srow;   // global batch row
    const int swc   = (tid & 3) * 4;       // word col base in A buf

    for (int t = 0; t < T_STEPS; ++t) {
        const float* __restrict__ x_t   = x_all + (size_t)t * BATCH * INP;
        const float* __restrict__ h_in  = (t & 1) ? g_h1 : g_h0;
        float*       __restrict__ h_out = (t & 1) ? g_h0 : g_h1;

        float d[2][2][4];
#pragma unroll
        for (int mf = 0; mf < 2; ++mf)
#pragma unroll
            for (int nf = 0; nf < 2; ++nf)
#pragma unroll
                for (int q = 0; q < 4; ++q) d[mf][nf][q] = 0.f;

        // ---- stage chunk 0 (pure x) into buffer 0 ----
        float2 pf[4];
        {
            const float* src = x_t + (size_t)brow * INP + skoff;
#pragma unroll
            for (int i = 0; i < 4; ++i) pf[i] = *(const float2*)(src + 2 * i);
#pragma unroll
            for (int i = 0; i < 4; ++i) {
                uint32_t wh, wl; split2(pf[i], wh, wl);
                Ab[(0) * BT * A_STRIDE + srow * A_STRIDE + swc + i] = wh;
                Ab[(1) * BT * A_STRIDE + srow * A_STRIDE + swc + i] = wl;
            }
        }
        __syncthreads();

        int buf = 0;
        for (int c = 0; c < NCH; ++c) {
            // prefetch next chunk into registers
            if (c < NCH - 1) {
                int kg = (c + 1) * KC + skoff;
                const float* src = (kg < INP)
                    ? (x_t  + (size_t)brow * INP + kg)
                    : (h_in + (size_t)brow * HID + (kg - INP));
#pragma unroll
                for (int i = 0; i < 4; ++i) pf[i] = *(const float2*)(src + 2 * i);
            }

            // MMA over the 2 k-steps (16 each) of this chunk
            const int base_h = (buf * 2 + 0) * BT * A_STRIDE;
            const int base_l = (buf * 2 + 1) * BT * A_STRIDE;
#pragma unroll
            for (int ks = 0; ks < 2; ++ks) {
                const int gw  = c * 16 + ks * 8 + lr4;   // weight word col
                uint32_t bh[2][2], bl[2][2];
#pragma unroll
                for (int nf = 0; nf < 2; ++nf) {
                    int r = wn * 16 + nf * 8 + lq;
                    bh[nf][0] = Whi[r * W_STRIDE + gw];
                    bh[nf][1] = Whi[r * W_STRIDE + gw + 4];
                    bl[nf][0] = Wlo[r * W_STRIDE + gw];
                    bl[nf][1] = Wlo[r * W_STRIDE + gw + 4];
                }
                const int wc0 = ks * 8 + lr4;
#pragma unroll
                for (int mf = 0; mf < 2; ++mf) {
                    int m0 = wm * 32 + mf * 16 + lq;
                    uint32_t ah[4], al[4];
                    ah[0] = Ab[base_h +  m0      * A_STRIDE + wc0];
                    ah[1] = Ab[base_h + (m0 + 8) * A_STRIDE + wc0];
                    ah[2] = Ab[base_h +  m0      * A_STRIDE + wc0 + 4];
                    ah[3] = Ab[base_h + (m0 + 8) * A_STRIDE + wc0 + 4];
                    al[0] = Ab[base_l +  m0      * A_STRIDE + wc0];
                    al[1] = Ab[base_l + (m0 + 8) * A_STRIDE + wc0];
                    al[2] = Ab[base_l +  m0      * A_STRIDE + wc0 + 4];
                    al[3] = Ab[base_l + (m0 + 8) * A_STRIDE + wc0 + 4];
#pragma unroll
                    for (int nf = 0; nf < 2; ++nf) {
                        MMA_BF16(d[mf][nf], ah, bh[nf][0], bh[nf][1]);  // hi*hi
                        MMA_BF16(d[mf][nf], ah, bl[nf][0], bl[nf][1]);  // hi*lo
                        MMA_BF16(d[mf][nf], al, bh[nf][0], bh[nf][1]);  // lo*hi
                    }
                }
            }

            // commit prefetched chunk into the other buffer
            if (c < NCH - 1) {
                int nbuf = buf ^ 1;
#pragma unroll
                for (int i = 0; i < 4; ++i) {
                    uint32_t wh, wl; split2(pf[i], wh, wl);
                    Ab[(nbuf * 2 + 0) * BT * A_STRIDE + srow * A_STRIDE + swc + i] = wh;
                    Ab[(nbuf * 2 + 1) * BT * A_STRIDE + srow * A_STRIDE + swc + i] = wl;
                }
            }
            __syncthreads();
            buf ^= 1;
        }

        // ---- spill accumulators to SMEM gates buffer (overlays A bufs) ----
#pragma unroll
        for (int mf = 0; mf < 2; ++mf)
#pragma unroll
            for (int nf = 0; nf < 2; ++nf) {
                int m = wm * 32 + mf * 16 + lq;
                int n = wn * 16 + nf * 8 + lr4 * 2;
                gates[ m      * G_STRIDE + n    ] = d[mf][nf][0];
                gates[ m      * G_STRIDE + n + 1] = d[mf][nf][1];
                gates[(m + 8) * G_STRIDE + n    ] = d[mf][nf][2];
                gates[(m + 8) * G_STRIDE + n + 1] = d[mf][nf][3];
            }
        __syncthreads();

        // ---- fused LSTM epilogue: thread owns 4 (b, j) cells ----
        {
            int b  = tid >> 2;
            int bg = bTile * BT + b;
#pragma unroll
            for (int i = 0; i < 4; ++i) {
                int j  = (tid & 3) * 4 + i;
                float gi = gates[b * G_STRIDE + j]      + bias_s[j];
                float gf = gates[b * G_STRIDE + 16 + j] + bias_s[16 + j];
                float gg = gates[b * G_STRIDE + 32 + j] + bias_s[32 + j];
                float go = gates[b * G_STRIDE + 48 + j] + bias_s[48 + j];
                float iv = 1.f / (1.f + expf(-gi));
                float fv = 1.f / (1.f + expf(-gf));
                float gv = tanhf(gg);
                float ov = 1.f / (1.f + expf(-go));
                int   jg = jTile * JT + j;
                size_t idx = (size_t)bg * HID + jg;
                float cn = fv * g_c[idx] + iv * gv;
                g_c[idx]   = cn;
                h_out[idx] = ov * tanhf(cn);
            }
        }

        // ---- grid barrier (sense-reversing): publish h_out to all blocks ----
        __syncthreads();
        if (tid == 0) {
            int ls = *s_ls ^ 1;
            *s_ls = ls;
            __threadfence();
            if (atomicAdd(&g_count, 1) == NBLK - 1) {
                g_count = 0;
                __threadfence();
                g_sense = ls;
            } else {
                while (g_sense != ls) { }
                __threadfence();
            }
        }
        __syncthreads();
    }
}

// out[b] = h_last[b] . W_dec + b_dec   (h_last lives in g_h0 after 2048 steps)
__global__ void decode_kernel(const float* __restrict__ W_dec,
                              const float* __restrict__ b_dec,
                              float* __restrict__ out)
{
    int b = blockIdx.x;
    float s = 0.f;
    for (int k = threadIdx.x; k < HID; k += 128)
        s += g_h0[(size_t)b * HID + k] * W_dec[k];
    __shared__ float red[128];
    red[threadIdx.x] = s;
    __syncthreads();
#pragma unroll
    for (int off = 64; off > 0; off >>= 1) {
        if (threadIdx.x < off) red[threadIdx.x] += red[threadIdx.x + off];
        __syncthreads();
    }
    if (threadIdx.x == 0) out[b] = red[0] + b_dec[0];
}

extern "C" void kernel_launch(void* const* d_in, const int* in_sizes, int n_in,
                              void* d_out, int out_size)
{
    (void)in_sizes; (void)n_in; (void)out_size;
    const float* x     = (const float*)d_in[0];  // [T, B, I]
    const float* h0    = (const float*)d_in[1];  // [B, H]
    const float* c0    = (const float*)d_in[2];  // [B, H]
    const float* W_ih  = (const float*)d_in[3];  // [4H, I]
    const float* W_hh  = (const float*)d_in[4];  // [4H, H]
    const float* b_ih  = (const float*)d_in[5];  // [4H]
    const float* b_hh  = (const float*)d_in[6];  // [4H]
    const float* W_dec = (const float*)d_in[7];  // [1, H]
    const float* b_dec = (const float*)d_in[8];  // [1]
    float* out = (float*)d_out;                  // [B, 1]

    static bool attr_set = false;
    if (!attr_set) {
        cudaFuncSetAttribute(lstm_tc_kernel,
                             cudaFuncAttributeMaxDynamicSharedMemorySize, SMEM_BYTES);
        attr_set = true;
    }

    init_state_kernel<<<(BATCH * HID + 255) / 256, 256>>>(h0, c0);

    dim3 grid(HID / JT, BATCH / BT);   // (32, 4) = 128 blocks, all co-resident
    lstm_tc_kernel<<<grid, 256, SMEM_BYTES>>>(x, W_ih, W_hh, b_ih, b_hh);

    decode_kernel<<<BATCH, 128>>>(W_dec, b_dec, out);
}

// round 6
// speedup vs baseline: 2.1057x; 1.0154x over previous
#include <cuda_runtime.h>
#include <cuda_bf16.h>
#include <math.h>
#include <stdint.h>

// Problem dims (fixed by dataset)
#define T_STEPS 2048
#define BATCH   256
#define INP     256
#define HID     512
#define KTOT    768            // concat K: [x_t | h]

// Partition: block = (jTile, bTile): 16 hidden cols x 64 batch rows
#define JT 16                  // hidden columns per block
#define BT 64                  // batch rows per block
#define NROWS 64               // gate rows per block = 4 gates * JT
#define KC 32                  // K chunk staged per iteration
#define NCH (KTOT / KC)        // 24 chunks
#define NBLK 128               // 32 x 4 grid, all co-resident (<=148 SMs)

// SMEM strides (in 32-bit words), padded for conflict-free fragment loads
#define W_STRIDE 388           // 384 words (768 bf16) + 4 pad  -> stride%32==4
#define A_STRIDE 20            // 16 words (32 bf16)  + 4 pad  -> stride%32==20
#define G_STRIDE 65            // gates buffer row stride (floats)

// SMEM layout (bytes)
#define SZ_W      (NROWS * W_STRIDE * 4)            // 99,328
#define OFF_WHI   0
#define OFF_WLO   (OFF_WHI + SZ_W)                  // 99,328
#define OFF_ABUF  (OFF_WLO + SZ_W)                  // 198,656
#define SZ_ABUF   (2 * 2 * BT * A_STRIDE * 4)       // 20,480 (dbuf x hi/lo x 64 x 20)
#define OFF_GATES OFF_ABUF                          // overlay (64*65*4 = 16,640 <= 20,480)
#define OFF_BIAS  (OFF_ABUF + SZ_ABUF)              // 219,136
#define OFF_SENSE (OFF_BIAS + NROWS * 4)            // 219,392
#define SMEM_BYTES (OFF_SENSE + 16)                 // 219,408

// Persistent state (device globals: allocation-free scratch)
__device__ float g_h0[BATCH * HID];
__device__ float g_h1[BATCH * HID];
__device__ float g_c [BATCH * HID];
__device__ volatile int g_sense;   // zero-init
__device__ int          g_count;   // zero-init

__global__ void init_state_kernel(const float* __restrict__ h0,
                                  const float* __restrict__ c0) {
    int i = blockIdx.x * blockDim.x + threadIdx.x;
    if (i < BATCH * HID) { g_h0[i] = h0[i]; g_c[i] = c0[i]; }
}

__device__ __forceinline__ uint32_t b2u(__nv_bfloat162 v) {
    return *reinterpret_cast<uint32_t*>(&v);
}

// split fp32 pair -> (hi bf16x2 word, lo bf16x2 word); low 16 bits = first (even-k) element
__device__ __forceinline__ void split2(float2 v, uint32_t& wh, uint32_t& wl) {
    __nv_bfloat162 hi2 = __floats2bfloat162_rn(v.x, v.y);
    float lx = v.x - __bfloat162float(__low2bfloat16(hi2));
    float ly = v.y - __bfloat162float(__high2bfloat16(hi2));
    __nv_bfloat162 lo2 = __floats2bfloat162_rn(lx, ly);
    wh = b2u(hi2); wl = b2u(lo2);
}

#define MMA_BF16(D, A, B0, B1)                                              \
    asm volatile("mma.sync.aligned.m16n8k16.row.col.f32.bf16.bf16.f32 "     \
                 "{%0,%1,%2,%3}, {%4,%5,%6,%7}, {%8,%9}, {%0,%1,%2,%3};"    \
                 : "+f"((D)[0]), "+f"((D)[1]), "+f"((D)[2]), "+f"((D)[3])   \
                 : "r"((A)[0]), "r"((A)[1]), "r"((A)[2]), "r"((A)[3]),      \
                   "r"(B0), "r"(B1));

// Persistent fused LSTM: tensor-core GEMM (bf16x3 ~ fp32), SMEM-resident weights,
// grid barrier between timesteps. Grid (32, 4) x 256 threads.
__global__ __launch_bounds__(256, 1)
void lstm_tc_kernel(const float* __restrict__ x_all,  // [T, BATCH, INP]
                    const float* __restrict__ W_ih,   // [4*HID, INP]
                    const float* __restrict__ W_hh,   // [4*HID, HID]
                    const float* __restrict__ b_ih,   // [4*HID]
                    const float* __restrict__ b_hh)   // [4*HID]
{
    extern __shared__ char sm[];
    uint32_t* Whi    = (uint32_t*)(sm + OFF_WHI);
    uint32_t* Wlo    = (uint32_t*)(sm + OFF_WLO);
    uint32_t* Ab     = (uint32_t*)(sm + OFF_ABUF);   // [(buf*2+hl)*BT + row]*A_STRIDE + col
    float*    gates  = (float*)   (sm + OFF_GATES);  // overlay on Ab
    float*    bias_s = (float*)   (sm + OFF_BIAS);
    int*      s_ls   = (int*)     (sm + OFF_SENSE);

    const int tid  = threadIdx.x;
    const int lane = tid & 31, warp = tid >> 5;
    const int wm = warp & 1;        // batch-half of the 64x64 tile
    const int wn = warp >> 1;       // 0..3: 16-gatecol slice
    const int lq  = lane >> 2;      // 0..7
    const int lr4 = lane & 3;       // 0..3
    const int jTile = blockIdx.x;   // 0..31
    const int bTile = blockIdx.y;   // 0..3

    // ---- one-time: load + split weights into SMEM (rows r = tt*16 + jj) ----
    {
        int r  = tid >> 2;                        // 0..63
        int grow = (r >> 4) * HID + jTile * JT + (r & 15);
        int kbase = (tid & 3) * 192;
        for (int i = 0; i < 96; ++i) {
            int k = kbase + 2 * i;
            float2 v = (k < INP)
                ? *(const float2*)(W_ih + (size_t)grow * INP + k)
                : *(const float2*)(W_hh + (size_t)grow * HID + (k - INP));
            uint32_t wh, wl; split2(v, wh, wl);
            Whi[r * W_STRIDE + k / 2] = wh;
            Wlo[r * W_STRIDE + k / 2] = wl;
        }
        if (tid < NROWS) {
            int gr = (tid >> 4) * HID + jTile * JT + (tid & 15);
            bias_s[tid] = b_ih[gr] + b_hh[gr];
        }
        if (tid == 0) *s_ls = g_sense;
    }
    __syncthreads();

    // staging assignment: 4 threads per batch row, 8 k-floats each
    const int srow  = tid >> 2;            // 0..63
    const int skoff = (tid & 3) * 8;       // k offset within chunk
    const int brow  = bTile * BT + srow;   // global batch row
    const int swc   = (tid & 3) * 4;       // word col base in A buf

    for (int t = 0; t < T_STEPS; ++t) {
        const float* __restrict__ x_t   = x_all + (size_t)t * BATCH * INP;
        const float* __restrict__ h_in  = (t & 1) ? g_h1 : g_h0;
        float*       __restrict__ h_out = (t & 1) ? g_h0 : g_h1;

        float d[2][2][4];
#pragma unroll
        for (int mf = 0; mf < 2; ++mf)
#pragma unroll
            for (int nf = 0; nf < 2; ++nf)
#pragma unroll
                for (int q = 0; q < 4; ++q) d[mf][nf][q] = 0.f;

        // ---- stage chunk 0 (pure x) into buffer 0 ----
        float2 pf[4];
        {
            const float* src = x_t + (size_t)brow * INP + skoff;
#pragma unroll
            for (int i = 0; i < 4; ++i) pf[i] = *(const float2*)(src + 2 * i);
#pragma unroll
            for (int i = 0; i < 4; ++i) {
                uint32_t wh, wl; split2(pf[i], wh, wl);
                Ab[(0) * BT * A_STRIDE + srow * A_STRIDE + swc + i] = wh;
                Ab[(1) * BT * A_STRIDE + srow * A_STRIDE + swc + i] = wl;
            }
        }
        __syncthreads();

        int buf = 0;
        for (int c = 0; c < NCH; ++c) {
            // prefetch next chunk into registers
            if (c < NCH - 1) {
                int kg = (c + 1) * KC + skoff;
                const float* src = (kg < INP)
                    ? (x_t  + (size_t)brow * INP + kg)
                    : (h_in + (size_t)brow * HID + (kg - INP));
#pragma unroll
                for (int i = 0; i < 4; ++i) pf[i] = *(const float2*)(src + 2 * i);
            }

            // MMA over the 2 k-steps (16 each) of this chunk
            const int base_h = (buf * 2 + 0) * BT * A_STRIDE;
            const int base_l = (buf * 2 + 1) * BT * A_STRIDE;
#pragma unroll
            for (int ks = 0; ks < 2; ++ks) {
                const int gw  = c * 16 + ks * 8 + lr4;   // weight word col
                uint32_t bh[2][2], bl[2][2];
#pragma unroll
                for (int nf = 0; nf < 2; ++nf) {
                    int r = wn * 16 + nf * 8 + lq;
                    bh[nf][0] = Whi[r * W_STRIDE + gw];
                    bh[nf][1] = Whi[r * W_STRIDE + gw + 4];
                    bl[nf][0] = Wlo[r * W_STRIDE + gw];
                    bl[nf][1] = Wlo[r * W_STRIDE + gw + 4];
                }
                const int wc0 = ks * 8 + lr4;
#pragma unroll
                for (int mf = 0; mf < 2; ++mf) {
                    int m0 = wm * 32 + mf * 16 + lq;
                    uint32_t ah[4], al[4];
                    ah[0] = Ab[base_h +  m0      * A_STRIDE + wc0];
                    ah[1] = Ab[base_h + (m0 + 8) * A_STRIDE + wc0];
                    ah[2] = Ab[base_h +  m0      * A_STRIDE + wc0 + 4];
                    ah[3] = Ab[base_h + (m0 + 8) * A_STRIDE + wc0 + 4];
                    al[0] = Ab[base_l +  m0      * A_STRIDE + wc0];
                    al[1] = Ab[base_l + (m0 + 8) * A_STRIDE + wc0];
                    al[2] = Ab[base_l +  m0      * A_STRIDE + wc0 + 4];
                    al[3] = Ab[base_l + (m0 + 8) * A_STRIDE + wc0 + 4];
#pragma unroll
                    for (int nf = 0; nf < 2; ++nf) {
                        MMA_BF16(d[mf][nf], ah, bh[nf][0], bh[nf][1]);  // hi*hi
                        MMA_BF16(d[mf][nf], ah, bl[nf][0], bl[nf][1]);  // hi*lo
                        MMA_BF16(d[mf][nf], al, bh[nf][0], bh[nf][1]);  // lo*hi
                    }
                }
            }

            // commit prefetched chunk into the other buffer
            if (c < NCH - 1) {
                int nbuf = buf ^ 1;
#pragma unroll
                for (int i = 0; i < 4; ++i) {
                    uint32_t wh, wl; split2(pf[i], wh, wl);
                    Ab[(nbuf * 2 + 0) * BT * A_STRIDE + srow * A_STRIDE + swc + i] = wh;
                    Ab[(nbuf * 2 + 1) * BT * A_STRIDE + srow * A_STRIDE + swc + i] = wl;
                }
            }
            __syncthreads();
            buf ^= 1;
        }

        // ---- spill accumulators to SMEM gates buffer (overlays A bufs) ----
#pragma unroll
        for (int mf = 0; mf < 2; ++mf)
#pragma unroll
            for (int nf = 0; nf < 2; ++nf) {
                int m = wm * 32 + mf * 16 + lq;
                int n = wn * 16 + nf * 8 + lr4 * 2;
                gates[ m      * G_STRIDE + n    ] = d[mf][nf][0];
                gates[ m      * G_STRIDE + n + 1] = d[mf][nf][1];
                gates[(m + 8) * G_STRIDE + n    ] = d[mf][nf][2];
                gates[(m + 8) * G_STRIDE + n + 1] = d[mf][nf][3];
            }
        __syncthreads();

        // ---- fused LSTM epilogue: thread owns 4 (b, j) cells ----
        {
            int b  = tid >> 2;
            int bg = bTile * BT + b;
#pragma unroll
            for (int i = 0; i < 4; ++i) {
                int j  = (tid & 3) * 4 + i;
                float gi = gates[b * G_STRIDE + j]      + bias_s[j];
                float gf = gates[b * G_STRIDE + 16 + j] + bias_s[16 + j];
                float gg = gates[b * G_STRIDE + 32 + j] + bias_s[32 + j];
                float go = gates[b * G_STRIDE + 48 + j] + bias_s[48 + j];
                float iv = 1.f / (1.f + expf(-gi));
                float fv = 1.f / (1.f + expf(-gf));
                float gv = tanhf(gg);
                float ov = 1.f / (1.f + expf(-go));
                int   jg = jTile * JT + j;
                size_t idx = (size_t)bg * HID + jg;
                float cn = fv * g_c[idx] + iv * gv;
                g_c[idx]   = cn;
                h_out[idx] = ov * tanhf(cn);
            }
        }

        // ---- grid barrier (sense-reversing): publish h_out to all blocks ----
        __syncthreads();
        if (tid == 0) {
            int ls = *s_ls ^ 1;
            *s_ls = ls;
            __threadfence();
            if (atomicAdd(&g_count, 1) == NBLK - 1) {
                g_count = 0;
                __threadfence();
                g_sense = ls;
            } else {
                while (g_sense != ls) { }
                __threadfence();
            }
        }
        __syncthreads();
    }
}

// out[b] = h_last[b] . W_dec + b_dec   (h_last lives in g_h0 after 2048 steps)
__global__ void decode_kernel(const float* __restrict__ W_dec,
                              const float* __restrict__ b_dec,
                              float* __restrict__ out)
{
    int b = blockIdx.x;
    float s = 0.f;
    for (int k = threadIdx.x; k < HID; k += 128)
        s += g_h0[(size_t)b * HID + k] * W_dec[k];
    __shared__ float red[128];
    red[threadIdx.x] = s;
    __syncthreads();
#pragma unroll
    for (int off = 64; off > 0; off >>= 1) {
        if (threadIdx.x < off) red[threadIdx.x] += red[threadIdx.x + off];
        __syncthreads();
    }
    if (threadIdx.x == 0) out[b] = red[0] + b_dec[0];
}

extern "C" void kernel_launch(void* const* d_in, const int* in_sizes, int n_in,
                              void* d_out, int out_size)
{
    (void)in_sizes; (void)n_in; (void)out_size;
    const float* x     = (const float*)d_in[0];  // [T, B, I]
    const float* h0    = (const float*)d_in[1];  // [B, H]
    const float* c0    = (const float*)d_in[2];  // [B, H]
    const float* W_ih  = (const float*)d_in[3];  // [4H, I]
    const float* W_hh  = (const float*)d_in[4];  // [4H, H]
    const float* b_ih  = (const float*)d_in[5];  // [4H]
    const float* b_hh  = (const float*)d_in[6];  // [4H]
    const float* W_dec = (const float*)d_in[7];  // [1, H]
    const float* b_dec = (const float*)d_in[8];  // [1]
    float* out = (float*)d_out;                  // [B, 1]

    static bool attr_set = false;
    if (!attr_set) {
        cudaFuncSetAttribute(lstm_tc_kernel,
                             cudaFuncAttributeMaxDynamicSharedMemorySize, SMEM_BYTES);
        attr_set = true;
    }

    init_state_kernel<<<(BATCH * HID + 255) / 256, 256>>>(h0, c0);

    dim3 grid(HID / JT, BATCH / BT);   // (32, 4) = 128 blocks, all co-resident
    lstm_tc_kernel<<<grid, 256, SMEM_BYTES>>>(x, W_ih, W_hh, b_ih, b_hh);

    decode_kernel<<<BATCH, 128>>>(W_dec, b_dec, out);
}